// round 13
// baseline (speedup 1.0000x reference)
#include <cuda_runtime.h>
#include <cuda_bf16.h>
#include <cstdint>

// ===== Problem constants =====
#define N_NODES 8192
#define F_DIM   64
#define C_DIM   10

// ===== Big GEMM tiling (A[8192x8192] @ Y[8192x64]) =====
#define BM 64
#define BN 64
#define BK 32
#define SPLITK 8
#define KSLICE (N_NODES / SPLITK)   // 1024
#define KTILES (KSLICE / BK)        // 32
#define AS_STRIDE (BK + 4)          // 36 floats: kills 32-float-stride bank conflicts, keeps 16B align

// ===== Scratch (device globals: no cudaMalloc allowed) =====
__device__ float g_deg[N_NODES];                               // 32 KB
__device__ float g_bufY[N_NODES * F_DIM];                      // 2 MB  (d ⊙ (x @ W))
__device__ float g_bufX[N_NODES * F_DIM];                      // 2 MB  (layer activations)
__device__ float g_bufP[SPLITK * N_NODES * F_DIM];             // 16 MB (split-K partials)

// ---------------------------------------------------------------------------
// cp.async helper (16B, L1-bypass: A is streamed, Y is L2-resident anyway)
// ---------------------------------------------------------------------------
__device__ __forceinline__ void cp_async16(void* smem_dst, const void* gmem_src) {
    unsigned s = (unsigned)__cvta_generic_to_shared(smem_dst);
    asm volatile("cp.async.cg.shared.global [%0], [%1], 16;" :: "r"(s), "l"(gmem_src));
}

// ---------------------------------------------------------------------------
// Kernel 1: d[i] = rowsum(A)[i] > 0 ? rsqrt(rowsum) : 0
// One block per row, float4 streaming, block reduce. ~256 MB read.
// ---------------------------------------------------------------------------
__global__ __launch_bounds__(256) void rowsum_kernel(const float* __restrict__ A) {
    int row = blockIdx.x;
    const float4* arow = reinterpret_cast<const float4*>(A + (size_t)row * N_NODES);
    float s = 0.f;
    #pragma unroll 4
    for (int i = threadIdx.x; i < N_NODES / 4; i += 256) {
        float4 v = arow[i];
        s += (v.x + v.y) + (v.z + v.w);
    }
    #pragma unroll
    for (int o = 16; o > 0; o >>= 1) s += __shfl_down_sync(0xffffffffu, s, o);

    __shared__ float ws[8];
    int lane = threadIdx.x & 31, w = threadIdx.x >> 5;
    if (lane == 0) ws[w] = s;
    __syncthreads();
    if (w == 0) {
        s = (lane < 8) ? ws[lane] : 0.f;
        #pragma unroll
        for (int o = 4; o > 0; o >>= 1) s += __shfl_down_sync(0xffffffffu, s, o);
        if (lane == 0) g_deg[row] = (s > 0.f) ? rsqrtf(s) : 0.f;
    }
}

// ---------------------------------------------------------------------------
// Kernel 2: Y[i,:] = d[i] * (X[i,:] @ W)   (W is 64x64, fits in smem)
// 4 rows per block, 256 threads = one output element each.
// ---------------------------------------------------------------------------
__global__ __launch_bounds__(256) void feat_mm_kernel(const float* __restrict__ X,
                                                      const float* __restrict__ W,
                                                      float* __restrict__ Y) {
    __shared__ float Ws[F_DIM][F_DIM];  // 16 KB
    __shared__ float Xs[4][F_DIM];
    int t = threadIdx.x;

    const float4* W4 = reinterpret_cast<const float4*>(W);
    float4* Ws4 = reinterpret_cast<float4*>(&Ws[0][0]);
    #pragma unroll
    for (int i = 0; i < (F_DIM * F_DIM / 4) / 256; i++) Ws4[t + 256 * i] = W4[t + 256 * i];

    int row0 = blockIdx.x * 4;
    const float4* X4 = reinterpret_cast<const float4*>(X + (size_t)row0 * F_DIM);
    if (t < 4 * F_DIM / 4) reinterpret_cast<float4*>(&Xs[0][0])[t] = X4[t];
    __syncthreads();

    int r = t >> 6;          // 0..3
    int c = t & 63;          // 0..63
    float acc = 0.f;
    #pragma unroll
    for (int k = 0; k < F_DIM; k++) acc = fmaf(Xs[r][k], Ws[k][c], acc);
    int row = row0 + r;
    Y[(size_t)row * F_DIM + c] = acc * g_deg[row];
}

// ---------------------------------------------------------------------------
// Kernel 3: the big one. P[kz] = A[:, kz-slice] @ Y[kz-slice, :]  (split-K)
// BM=64 x BN=64 tile, BK=32, 256 threads, 4x4 register tile per thread,
// cp.async double-buffered. Grid (128, SPLITK) = 1024 CTAs.
// ---------------------------------------------------------------------------
__device__ __forceinline__ void load_tiles(float (*As)[AS_STRIDE], float (*Ys)[BN],
                                           const float* Ag, const float* Yg,
                                           int kt, int t) {
    const float* Ab = Ag + kt * BK;
    #pragma unroll
    for (int i = 0; i < 2; i++) {
        int f = t + 256 * i;             // 0..511 : 64 rows x 8 float4
        int r = f >> 3, c = (f & 7) << 2;
        cp_async16(&As[r][c], Ab + (size_t)r * N_NODES + c);
    }
    const float* Yb = Yg + kt * BK * F_DIM;
    #pragma unroll
    for (int i = 0; i < 2; i++) {
        int f = t + 256 * i;             // 0..511 : 32 rows x 16 float4
        int r = f >> 4, c = (f & 15) << 2;
        cp_async16(&Ys[r][c], Yb + r * F_DIM + c);
    }
    asm volatile("cp.async.commit_group;" ::: "memory");
}

__global__ __launch_bounds__(256) void gcn_aggr_kernel(const float* __restrict__ A,
                                                       const float* __restrict__ Y,
                                                       float* __restrict__ P) {
    __shared__ float As[2][BM][AS_STRIDE];   // 18 KB
    __shared__ float Ys[2][BK][BN];          // 16 KB

    int t = threadIdx.x;
    int row0 = blockIdx.x * BM;
    int k0 = blockIdx.y * KSLICE;
    const float* Ag = A + (size_t)row0 * N_NODES + k0;
    const float* Yg = Y + (size_t)k0 * F_DIM;

    float acc[4][4] = {};
    int ty = t >> 4, tx = t & 15;

    load_tiles(As[0], Ys[0], Ag, Yg, 0, t);

    #pragma unroll 1
    for (int kt = 0; kt < KTILES; kt++) {
        int st = kt & 1;
        if (kt + 1 < KTILES) {
            load_tiles(As[st ^ 1], Ys[st ^ 1], Ag, Yg, kt + 1, t);
            asm volatile("cp.async.wait_group 1;" ::: "memory");
        } else {
            asm volatile("cp.async.wait_group 0;" ::: "memory");
        }
        __syncthreads();

        const float (*Asc)[AS_STRIDE] = As[st];
        const float (*Ysc)[BN] = Ys[st];
        #pragma unroll
        for (int k = 0; k < BK; k++) {
            float a0 = Asc[ty * 4 + 0][k];
            float a1 = Asc[ty * 4 + 1][k];
            float a2 = Asc[ty * 4 + 2][k];
            float a3 = Asc[ty * 4 + 3][k];
            float4 y = *reinterpret_cast<const float4*>(&Ysc[k][tx << 2]);
            acc[0][0] = fmaf(a0, y.x, acc[0][0]);
            acc[0][1] = fmaf(a0, y.y, acc[0][1]);
            acc[0][2] = fmaf(a0, y.z, acc[0][2]);
            acc[0][3] = fmaf(a0, y.w, acc[0][3]);
            acc[1][0] = fmaf(a1, y.x, acc[1][0]);
            acc[1][1] = fmaf(a1, y.y, acc[1][1]);
            acc[1][2] = fmaf(a1, y.z, acc[1][2]);
            acc[1][3] = fmaf(a1, y.w, acc[1][3]);
            acc[2][0] = fmaf(a2, y.x, acc[2][0]);
            acc[2][1] = fmaf(a2, y.y, acc[2][1]);
            acc[2][2] = fmaf(a2, y.z, acc[2][2]);
            acc[2][3] = fmaf(a2, y.w, acc[2][3]);
            acc[3][0] = fmaf(a3, y.x, acc[3][0]);
            acc[3][1] = fmaf(a3, y.y, acc[3][1]);
            acc[3][2] = fmaf(a3, y.z, acc[3][2]);
            acc[3][3] = fmaf(a3, y.w, acc[3][3]);
        }
        __syncthreads();
    }

    float* Pb = P + (size_t)blockIdx.y * (N_NODES * F_DIM) + (size_t)row0 * F_DIM;
    #pragma unroll
    for (int i = 0; i < 4; i++) {
        float4 v = make_float4(acc[i][0], acc[i][1], acc[i][2], acc[i][3]);
        *reinterpret_cast<float4*>(&Pb[(size_t)(ty * 4 + i) * F_DIM + (tx << 2)]) = v;
    }
}

// ---------------------------------------------------------------------------
// Kernel 4: split-K reduce + row scale + relu.  Xo = relu(d ⊙ Σ_s P[s])
// ---------------------------------------------------------------------------
__global__ __launch_bounds__(256) void reduce_relu_kernel(const float* __restrict__ P,
                                                          float* __restrict__ Xo) {
    int idx = blockIdx.x * 256 + threadIdx.x;   // float4 index over N*F/4 = 131072
    const float4* P4 = reinterpret_cast<const float4*>(P);
    float4 s = P4[idx];
    #pragma unroll
    for (int z = 1; z < SPLITK; z++) {
        float4 v = P4[(size_t)z * (N_NODES * F_DIM / 4) + idx];
        s.x += v.x; s.y += v.y; s.z += v.z; s.w += v.w;
    }
    int row = idx / (F_DIM / 4);
    float dd = g_deg[row];
    s.x = fmaxf(s.x * dd, 0.f);
    s.y = fmaxf(s.y * dd, 0.f);
    s.z = fmaxf(s.z * dd, 0.f);
    s.w = fmaxf(s.w * dd, 0.f);
    reinterpret_cast<float4*>(Xo)[idx] = s;
}

// ---------------------------------------------------------------------------
// Kernel 5: logits = X @ Wc + bc   (Wc 64x10)
// ---------------------------------------------------------------------------
__global__ __launch_bounds__(256) void logits_kernel(const float* __restrict__ X,
                                                     const float* __restrict__ Wc,
                                                     const float* __restrict__ bc,
                                                     float* __restrict__ out) {
    __shared__ float Ws[F_DIM][C_DIM];
    __shared__ float bs[C_DIM];
    int t = threadIdx.x;
    for (int i = t; i < F_DIM * C_DIM; i += 256) Ws[i / C_DIM][i % C_DIM] = Wc[i];
    if (t < C_DIM) bs[t] = bc[t];
    __syncthreads();

    int idx = blockIdx.x * 256 + t;   // 0 .. 81919 exactly (320 blocks)
    int row = idx / C_DIM;
    int c = idx % C_DIM;
    const float* xr = X + (size_t)row * F_DIM;
    float acc = bs[c];
    #pragma unroll
    for (int k = 0; k < F_DIM; k++) acc = fmaf(xr[k], Ws[k][c], acc);
    out[idx] = acc;
}

// ---------------------------------------------------------------------------
// Launch: graph-capturable, allocation-free, all on the default stream.
// Input order (metadata): A_tilde, emb, W1, W2, Wc, bc.
// ---------------------------------------------------------------------------
extern "C" void kernel_launch(void* const* d_in, const int* in_sizes, int n_in,
                              void* d_out, int out_size) {
    const float* A   = (const float*)d_in[0];
    const float* emb = (const float*)d_in[1];
    const float* W1  = (const float*)d_in[2];
    const float* W2  = (const float*)d_in[3];
    const float* Wc  = (const float*)d_in[4];
    const float* bc  = (const float*)d_in[5];
    float* out = (float*)d_out;

    float *bufY, *bufX, *bufP;
    cudaGetSymbolAddress((void**)&bufY, g_bufY);
    cudaGetSymbolAddress((void**)&bufX, g_bufX);
    cudaGetSymbolAddress((void**)&bufP, g_bufP);

    // d = rsqrt(rowsum(A)), 0 where rowsum <= 0
    rowsum_kernel<<<N_NODES, 256>>>(A);

    // Layer 1: Y = d ⊙ (emb @ W1);  X = relu(d ⊙ (A @ Y))
    feat_mm_kernel<<<N_NODES / 4, 256>>>(emb, W1, bufY);
    gcn_aggr_kernel<<<dim3(N_NODES / BM, SPLITK), 256>>>(A, bufY, bufP);
    reduce_relu_kernel<<<(N_NODES * F_DIM / 4) / 256, 256>>>(bufP, bufX);

    // Layer 2
    feat_mm_kernel<<<N_NODES / 4, 256>>>(bufX, W2, bufY);
    gcn_aggr_kernel<<<dim3(N_NODES / BM, SPLITK), 256>>>(A, bufY, bufP);
    reduce_relu_kernel<<<(N_NODES * F_DIM / 4) / 256, 256>>>(bufP, bufX);

    // logits = X @ Wc + bc
    logits_kernel<<<(N_NODES * C_DIM) / 256, 256>>>(bufX, Wc, bc, out);
}

// round 15
// speedup vs baseline: 2.3173x; 2.3173x over previous
#include <cuda_runtime.h>
#include <cuda_fp16.h>
#include <cstdint>

// ===== Problem constants =====
#define N_NODES 8192
#define F_DIM   64
#define C_DIM   10

// ===== HMMA GEMM tiling: A[8192x8192](fp16) @ Y(fp16, stored [F][N]) -> fp32 =====
#define BM 128
#define BN 64
#define BK 32                         // halves per k-tile (2 x k16 MMA steps)
#define GSPLIT 2                      // 64 x 2 = 128 CTAs (one wave on 148 SMs)
#define KSLICE (N_NODES / GSPLIT)     // 4096
#define KT (KSLICE / BK)              // 128 iterations
#define STAGES 4
#define LDS_H 40                      // smem row stride in halves (80 B): conflict-free ldmatrix
#define A_SMEM_B (BM * LDS_H * 2)     // 10240 B
#define B_SMEM_B (BN * LDS_H * 2)     // 5120 B
#define STAGE_B  (A_SMEM_B + B_SMEM_B)          // 15360 B
#define SMEM_TOTAL (STAGES * STAGE_B)           // 61440 B

// ===== Scratch (device globals: no cudaMalloc allowed) =====
__device__ float  g_deg[N_NODES];                      // 32 KB
__device__ __half g_Ah[(size_t)N_NODES * N_NODES];     // 128 MB: RNE fp16 copy of A
__device__ __half g_Yt[(size_t)F_DIM * N_NODES];       // 1 MB: Y^T (= col-major B), fp16
__device__ float  g_bufX[N_NODES * F_DIM];             // 2 MB
__device__ float  g_bufP[GSPLIT * N_NODES * F_DIM];    // 4 MB split-K partials

// ---------------------------------------------------------------------------
// helpers
// ---------------------------------------------------------------------------
__device__ __forceinline__ uint32_t smem_u32(const void* p) {
    return (uint32_t)__cvta_generic_to_shared(p);
}
__device__ __forceinline__ void cp_async16(uint32_t dst, const void* src) {
    asm volatile("cp.async.cg.shared.global [%0], [%1], 16;" :: "r"(dst), "l"(src));
}
__device__ __forceinline__ void cp_commit() {
    asm volatile("cp.async.commit_group;" ::: "memory");
}
__device__ __forceinline__ void ldsm_x4(uint32_t* r, uint32_t addr) {
    asm volatile("ldmatrix.sync.aligned.m8n8.x4.shared.b16 {%0,%1,%2,%3}, [%4];"
                 : "=r"(r[0]), "=r"(r[1]), "=r"(r[2]), "=r"(r[3]) : "r"(addr));
}
__device__ __forceinline__ void mma16816(float* c, const uint32_t* a, uint32_t b0, uint32_t b1) {
    asm volatile(
        "mma.sync.aligned.m16n8k16.row.col.f32.f16.f16.f32 "
        "{%0,%1,%2,%3}, {%4,%5,%6,%7}, {%8,%9}, {%0,%1,%2,%3};"
        : "+f"(c[0]), "+f"(c[1]), "+f"(c[2]), "+f"(c[3])
        : "r"(a[0]), "r"(a[1]), "r"(a[2]), "r"(a[3]), "r"(b0), "r"(b1));
}

// ---------------------------------------------------------------------------
// Kernel 1: rowsum -> d = rsqrt(s) (0 if s<=0), fused fp32->fp16 RNE convert
// ---------------------------------------------------------------------------
__global__ __launch_bounds__(256) void rowsum_convert_kernel(const float* __restrict__ A,
                                                             __half* __restrict__ Ah) {
    int row = blockIdx.x;
    const float4* arow = reinterpret_cast<const float4*>(A + (size_t)row * N_NODES);
    __half2* hrow = reinterpret_cast<__half2*>(Ah + (size_t)row * N_NODES);
    float s = 0.f;
    #pragma unroll 4
    for (int i = threadIdx.x; i < N_NODES / 4; i += 256) {
        float4 v = arow[i];
        s += (v.x + v.y) + (v.z + v.w);
        hrow[2 * i + 0] = __floats2half2_rn(v.x, v.y);
        hrow[2 * i + 1] = __floats2half2_rn(v.z, v.w);
    }
    #pragma unroll
    for (int o = 16; o > 0; o >>= 1) s += __shfl_down_sync(0xffffffffu, s, o);
    __shared__ float ws[8];
    int lane = threadIdx.x & 31, w = threadIdx.x >> 5;
    if (lane == 0) ws[w] = s;
    __syncthreads();
    if (w == 0) {
        s = (lane < 8) ? ws[lane] : 0.f;
        #pragma unroll
        for (int o = 4; o > 0; o >>= 1) s += __shfl_down_sync(0xffffffffu, s, o);
        if (lane == 0) g_deg[row] = (s > 0.f) ? rsqrtf(s) : 0.f;
    }
}

// ---------------------------------------------------------------------------
// Kernel 2: Yt[c][row] = fp16_rn( d[row] * (X[row,:] @ W)[c] )
// ---------------------------------------------------------------------------
__global__ __launch_bounds__(256) void feat_mm_kernel(const float* __restrict__ X,
                                                      const float* __restrict__ W,
                                                      __half* __restrict__ Yt) {
    __shared__ float Ws[F_DIM][F_DIM];
    __shared__ float Xs[4][F_DIM];
    int t = threadIdx.x;
    const float4* W4 = reinterpret_cast<const float4*>(W);
    float4* Ws4 = reinterpret_cast<float4*>(&Ws[0][0]);
    #pragma unroll
    for (int i = 0; i < (F_DIM * F_DIM / 4) / 256; i++) Ws4[t + 256 * i] = W4[t + 256 * i];
    int row0 = blockIdx.x * 4;
    const float4* X4 = reinterpret_cast<const float4*>(X + (size_t)row0 * F_DIM);
    if (t < 4 * F_DIM / 4) reinterpret_cast<float4*>(&Xs[0][0])[t] = X4[t];
    __syncthreads();
    int r = t >> 6, c = t & 63;
    float acc = 0.f;
    #pragma unroll
    for (int k = 0; k < F_DIM; k++) acc = fmaf(Xs[r][k], Ws[k][c], acc);
    int row = row0 + r;
    Yt[(size_t)c * N_NODES + row] = __float2half_rn(acc * g_deg[row]);
}

// ---------------------------------------------------------------------------
// Kernel 3: split-K HMMA GEMM.  P[split] = A16[:, slice] @ B[slice, :]
// B is g_Yt stored [N=F][K=N_NODES] row-major == col-major B (mma .col operand).
// 128x64 CTA tile, 8 warps (4x2), 4-stage cp.async ring.
// ---------------------------------------------------------------------------
__device__ __forceinline__ void load_tiles(uint32_t stage, const __half* Ag,
                                           const __half* Bg, int it, int t) {
    const __half* Ab = Ag + it * BK;
    #pragma unroll
    for (int i = 0; i < 2; i++) {
        int f = t + 256 * i;             // 512 chunks: 128 rows x 4x16B
        int r = f >> 2, c = f & 3;
        cp_async16(stage + r * (LDS_H * 2) + c * 16, Ab + (size_t)r * N_NODES + c * 8);
    }
    const __half* Bb = Bg + it * BK;
    {
        int n = t >> 2, c = t & 3;       // 256 chunks: 64 rows x 4x16B
        cp_async16(stage + A_SMEM_B + n * (LDS_H * 2) + c * 16,
                   Bb + (size_t)n * N_NODES + c * 8);
    }
    cp_commit();
}

__global__ __launch_bounds__(256, 1) void gcn_aggr_mma(const __half* __restrict__ Ah,
                                                       const __half* __restrict__ Yt,
                                                       float* __restrict__ P) {
    extern __shared__ __align__(16) char smem[];
    uint32_t sb = smem_u32(smem);
    int t = threadIdx.x, wid = t >> 5, lane = t & 31;

    int row0 = blockIdx.x * BM;
    int k0 = blockIdx.y * KSLICE;
    const __half* Ag = Ah + (size_t)row0 * N_NODES + k0;
    const __half* Bg = Yt + k0;

    int rbase = (wid >> 1) * 32;         // warp M offset (0,32,64,96)
    int cbase = (wid & 1) * 32;          // warp N offset (0,32)

    float acc[2][4][4] = {};

    // prologue: fill 3 stages
    #pragma unroll
    for (int p = 0; p < STAGES - 1; p++)
        load_tiles(sb + p * STAGE_B, Ag, Bg, p, t);

    // precomputed ldmatrix lane addressing (byte offsets within tile)
    int a_row_in16 = lane & 15;
    int a_half = (lane >> 4) << 4;                    // 0 or 16 bytes (8 halves)
    int b_row = (lane & 7) + ((lane >> 4) << 3);      // 0..15 within 16-n group
    int b_half = ((lane >> 3) & 1) << 4;

    #pragma unroll 1
    for (int it = 0; it < KT; it++) {
        uint32_t stage = sb + (it & (STAGES - 1)) * STAGE_B;

        if (it + STAGES - 1 < KT)
            load_tiles(sb + ((it + STAGES - 1) & (STAGES - 1)) * STAGE_B, Ag, Bg,
                       it + STAGES - 1, t);
        else
            cp_commit();                 // empty group keeps accounting exact

        asm volatile("cp.async.wait_group %0;" :: "n"(STAGES - 1) : "memory");
        __syncthreads();

        uint32_t As = stage;
        uint32_t Bs = stage + A_SMEM_B;

        #pragma unroll
        for (int ks = 0; ks < 2; ks++) {             // two k16 steps per BK=32
            uint32_t a[2][4], b[2][4];
            #pragma unroll
            for (int mi = 0; mi < 2; mi++)
                ldsm_x4(a[mi], As + (rbase + 16 * mi + a_row_in16) * (LDS_H * 2)
                                   + ks * 32 + a_half);
            #pragma unroll
            for (int nj = 0; nj < 2; nj++)
                ldsm_x4(b[nj], Bs + (cbase + 16 * nj + b_row) * (LDS_H * 2)
                                   + ks * 32 + b_half);
            #pragma unroll
            for (int mi = 0; mi < 2; mi++)
                #pragma unroll
                for (int nj = 0; nj < 4; nj++)
                    mma16816(acc[mi][nj], a[mi],
                             b[nj >> 1][(nj & 1) * 2], b[nj >> 1][(nj & 1) * 2 + 1]);
        }
        __syncthreads();
    }

    // Epilogue: store fp32 partials
    float* Pb = P + (size_t)blockIdx.y * (N_NODES * F_DIM);
    int gr = row0 + rbase + (lane >> 2);
    int gc = cbase + (lane & 3) * 2;
    #pragma unroll
    for (int mi = 0; mi < 2; mi++) {
        #pragma unroll
        for (int nj = 0; nj < 4; nj++) {
            int r = gr + mi * 16, c = gc + nj * 8;
            *reinterpret_cast<float2*>(&Pb[(size_t)r * F_DIM + c]) =
                make_float2(acc[mi][nj][0], acc[mi][nj][1]);
            *reinterpret_cast<float2*>(&Pb[(size_t)(r + 8) * F_DIM + c]) =
                make_float2(acc[mi][nj][2], acc[mi][nj][3]);
        }
    }
}

// ---------------------------------------------------------------------------
// Kernel 4: split-K reduce + row scale + relu.  Xo = relu(d ⊙ (P0 + P1))
// ---------------------------------------------------------------------------
__global__ __launch_bounds__(256) void reduce_relu_kernel(const float* __restrict__ P,
                                                          float* __restrict__ Xo) {
    int idx = blockIdx.x * 256 + threadIdx.x;
    const float4* P4 = reinterpret_cast<const float4*>(P);
    float4 a = P4[idx];
    float4 b = P4[(size_t)(N_NODES * F_DIM / 4) + idx];
    int row = idx / (F_DIM / 4);
    float dd = g_deg[row];
    float4 s;
    s.x = fmaxf((a.x + b.x) * dd, 0.f);
    s.y = fmaxf((a.y + b.y) * dd, 0.f);
    s.z = fmaxf((a.z + b.z) * dd, 0.f);
    s.w = fmaxf((a.w + b.w) * dd, 0.f);
    reinterpret_cast<float4*>(Xo)[idx] = s;
}

// ---------------------------------------------------------------------------
// Kernel 5: logits = X @ Wc + bc   (fp32, exact)
// ---------------------------------------------------------------------------
__global__ __launch_bounds__(256) void logits_kernel(const float* __restrict__ X,
                                                     const float* __restrict__ Wc,
                                                     const float* __restrict__ bc,
                                                     float* __restrict__ out) {
    __shared__ float Ws[F_DIM][C_DIM];
    __shared__ float bs[C_DIM];
    int t = threadIdx.x;
    for (int i = t; i < F_DIM * C_DIM; i += 256) Ws[i / C_DIM][i % C_DIM] = Wc[i];
    if (t < C_DIM) bs[t] = bc[t];
    __syncthreads();
    int idx = blockIdx.x * 256 + t;
    int row = idx / C_DIM, c = idx % C_DIM;
    const float* xr = X + (size_t)row * F_DIM;
    float acc = bs[c];
    #pragma unroll
    for (int k = 0; k < F_DIM; k++) acc = fmaf(xr[k], Ws[k][c], acc);
    out[idx] = acc;
}

// ---------------------------------------------------------------------------
// Launch: graph-capturable, allocation-free.
// Inputs: A_tilde, emb, W1, W2, Wc, bc.
// ---------------------------------------------------------------------------
extern "C" void kernel_launch(void* const* d_in, const int* in_sizes, int n_in,
                              void* d_out, int out_size) {
    const float* A   = (const float*)d_in[0];
    const float* emb = (const float*)d_in[1];
    const float* W1  = (const float*)d_in[2];
    const float* W2  = (const float*)d_in[3];
    const float* Wc  = (const float*)d_in[4];
    const float* bc  = (const float*)d_in[5];
    float* out = (float*)d_out;

    __half *Ah, *Yt;
    float *bufX, *bufP;
    cudaGetSymbolAddress((void**)&Ah,   g_Ah);
    cudaGetSymbolAddress((void**)&Yt,   g_Yt);
    cudaGetSymbolAddress((void**)&bufX, g_bufX);
    cudaGetSymbolAddress((void**)&bufP, g_bufP);

    cudaFuncSetAttribute(gcn_aggr_mma, cudaFuncAttributeMaxDynamicSharedMemorySize,
                         SMEM_TOTAL);

    // d = rsqrt(rowsum(A)); A -> fp16 RNE copy
    rowsum_convert_kernel<<<N_NODES, 256>>>(A, Ah);

    // Layer 1
    feat_mm_kernel<<<N_NODES / 4, 256>>>(emb, W1, Yt);
    gcn_aggr_mma<<<dim3(N_NODES / BM, GSPLIT), 256, SMEM_TOTAL>>>(Ah, Yt, bufP);
    reduce_relu_kernel<<<(N_NODES * F_DIM / 4) / 256, 256>>>(bufP, bufX);

    // Layer 2
    feat_mm_kernel<<<N_NODES / 4, 256>>>(bufX, W2, Yt);
    gcn_aggr_mma<<<dim3(N_NODES / BM, GSPLIT), 256, SMEM_TOTAL>>>(Ah, Yt, bufP);
    reduce_relu_kernel<<<(N_NODES * F_DIM / 4) / 256, 256>>>(bufP, bufX);

    // logits
    logits_kernel<<<(N_NODES * C_DIM) / 256, 256>>>(bufX, Wc, bc, out);
}